// round 8
// baseline (speedup 1.0000x reference)
#include <cuda_runtime.h>
#include <cuda_fp16.h>
#include <cstdint>
#include <math.h>

#define HH 128
#define WW 128
#define HW 16384
#define CC 16
#define NPTS 32
#define NLINES (5 * HW)
#define LOI_FLOATS (NLINES * (CC * NPTS))   // 41,943,040
#define J_OFF LOI_FLOATS
#define S_OFF (LOI_FLOATS + 600)
#define TOPK 300
#define NSEG 64
#define SEGSTRIDE 264                        // 8B keys; padded, 16B-aligned stride
#define GRID 592                             // 4 blocks/SM x 148 SMs (all resident)
#define NTILES 1024                          // 32x32 tiles of 4x4 pixels

// ---- device scratch ----
__device__ uint4 g_fthv[HW * 2];             // features fp16 (H,W,C): 32B/pixel
__device__ float4 g_geom[NLINES];            // per-line (ux,uy,vx,vy)
__device__ unsigned long long g_keys[NSEG * SEGSTRIDE];
__device__ int g_bcnt[NSEG];
__device__ unsigned g_bar  = 0;
__device__ unsigned g_tile = 0;
__device__ unsigned g_done = 0;

__device__ __forceinline__ float2 h2f(unsigned u) {
    __half2 h = *reinterpret_cast<const __half2*>(&u);
    return __half22float2(h);
}

// ---------------------------------------------------------------------------
// ONE fused persistent kernel: 592 blocks x 256 threads, 4 blocks/SM.
// ---------------------------------------------------------------------------
__global__ void __launch_bounds__(256, 4) hawp_kernel(
    const float* __restrict__ md,    // (3,H,W)
    const float* __restrict__ dis,   // (H,W)
    const float* __restrict__ res,   // (H,W)
    const float* __restrict__ f,     // (16,H,W)
    const float* __restrict__ jloc,  // (H,W)
    const float* __restrict__ joff,  // (2,H,W)
    float* __restrict__ out)
{
    __shared__ int s_cnt;
    __shared__ int s_tile;
    __shared__ int s_bc[NSEG];
    __shared__ int s_ps[NSEG + 1];

    const int tid = threadIdx.x;
    const int bid = blockIdx.x;

    // ================= Phase 1: prep (blocks 0..63) =================
    if (bid < NSEG) {
        if (tid == 0) s_cnt = 0;
        __syncthreads();

        const int p = bid * 256 + tid;
        const int yi = p >> 7;
        const int xi = p & 127;

        // transpose + fp16-convert features: (C,H,W) f32 -> (H,W,C) fp16
        {
            unsigned h[8];
#pragma unroll
            for (int k = 0; k < 8; k++) {
                float lo = f[(2 * k + 0) * HW + p];
                float hi = f[(2 * k + 1) * HW + p];
                __half2 hh = __floats2half2_rn(lo, hi);
                h[k] = *reinterpret_cast<unsigned*>(&hh);
            }
            g_fthv[p * 2 + 0] = make_uint4(h[0], h[1], h[2], h[3]);
            g_fthv[p * 2 + 1] = make_uint4(h[4], h[5], h[6], h[7]);
        }

        // line geometry (exact trig, once per pixel)
        const float md0 = md[p];
        const float md1 = md[HW + p];
        const float md2 = md[2 * HW + p];
        const float d0  = dis[p];
        const float rs  = res[p];

        float ss, cs;
        sincosf((md0 - 0.5f) * 6.2831853071795864f, &ss, &cs);
        const float yst = tanf(md1 * 1.5707963267948966f);
        const float yed = tanf(-md2 * 1.5707963267948966f);
        const float ax = cs - ss * yst, ay = ss + cs * yst;
        const float bx = cs - ss * yed, by = ss + cs * yed;
        const float fx = (float)xi, fy = (float)yi;

#pragma unroll
        for (int r = 0; r < 5; r++) {
            float dval = fminf(fmaxf(d0 + rs * (float)(r - 2), 0.0f), 1.0f);
            const float ds = dval * 5.0f;
            float4 g;
            g.x = fminf(fmaxf(ax * ds + fx, 0.0f), 127.0f);
            g.y = fminf(fmaxf(ay * ds + fy, 0.0f), 127.0f);
            g.z = fminf(fmaxf(bx * ds + fx, 0.0f), 127.0f);
            g.w = fminf(fmaxf(by * ds + fy, 0.0f), 127.0f);
            g_geom[r * HW + p] = g;
        }

        // 3x3 NMS + per-block compaction
        float a = jloc[p];
        float m = -INFINITY;
#pragma unroll
        for (int dy = -1; dy <= 1; dy++) {
#pragma unroll
            for (int dx = -1; dx <= 1; dx++) {
                int yy = yi + dy, xx = xi + dx;
                if (yy >= 0 && yy < HH && xx >= 0 && xx < WW)
                    m = fmaxf(m, jloc[yy * WW + xx]);
            }
        }
        if (a == m && a > 0.0f) {
            int pos = atomicAdd(&s_cnt, 1);
            g_keys[bid * SEGSTRIDE + pos] =
                ((unsigned long long)__float_as_uint(a) << 32) |
                (unsigned long long)(0xFFFFFFFFu - (unsigned)p);
        }
        __syncthreads();
        // zero-pad 8 slots past the end so the topk scan can read ull2 blindly
        int c0 = s_cnt;
        if (tid >= c0 && tid < c0 + 8)
            g_keys[bid * SEGSTRIDE + tid] = 0ULL;
        if (tid == 0) g_bcnt[bid] = c0;
    }

    // ================= grid barrier (self-cleaning across replays) ==========
    __threadfence();
    __syncthreads();
    if (tid == 0) {
        atomicAdd(&g_bar, 1u);
        while (atomicAdd(&g_bar, 0u) < GRID) { }
    }
    __syncthreads();
    __threadfence();

    // ================= Phase 2a: topk (blocks 0..15), keys read from L2/L1 ==
    if (bid < 16) {
        if (tid < NSEG) s_bc[tid] = g_bcnt[tid];
        __syncthreads();
        if (tid == 0) {
            int acc = 0;
#pragma unroll
            for (int b = 0; b < NSEG; b++) { s_ps[b] = acc; acc += s_bc[b]; }
            s_ps[NSEG] = acc;
        }
        __syncthreads();

        const int cnt = s_ps[NSEG];
        const int gid = bid * 256 + tid;
        if (gid < cnt) {
            // binary search for owning segment
            int lo = 0, hi = NSEG - 1;
            while (lo < hi) {
                int mid = (lo + hi + 1) >> 1;
                if (s_ps[mid] <= gid) lo = mid; else hi = mid - 1;
            }
            const unsigned long long mykey =
                g_keys[lo * SEGSTRIDE + (gid - s_ps[lo])];

            // rank by counting strictly-greater keys (keys unique)
            int rank = 0;
#pragma unroll 1
            for (int b = 0; b < NSEG; b++) {
                const int n2 = (s_bc[b] + 1) >> 1;   // ull2 count (padded w/ 0)
                const ulonglong2* kp =
                    (const ulonglong2*)(g_keys + b * SEGSTRIDE);
#pragma unroll 4
                for (int i = 0; i < n2; i++) {
                    ulonglong2 v = kp[i];
                    rank += (v.x > mykey) + (v.y > mykey);
                }
            }

            if (rank < TOPK) {
                unsigned idx = 0xFFFFFFFFu - (unsigned)(mykey & 0xFFFFFFFFull);
                float val = __uint_as_float((unsigned)(mykey >> 32));
                float fy = (float)(idx >> 7);
                float fx = (float)(idx & 127);
                out[J_OFF + 2 * rank + 0] = fx + joff[idx] + 0.5f;
                out[J_OFF + 2 * rank + 1] = fy + joff[HW + idx] + 0.5f;
                out[S_OFF + rank] = val;
            }
        }
        __syncthreads();
    }

    // ================= Phase 2b: loi over dynamically-stolen 4x4 tiles ======
    const int warp = tid >> 5;
    const int lane = tid & 31;
    const float t   = (float)lane * (1.0f / 31.0f);
    const float omt = 1.0f - t;

    for (;;) {
        __syncthreads();
        if (tid == 0) s_tile = (int)atomicAdd(&g_tile, 1u);
        __syncthreads();
        const int tile = s_tile;
        if (tile >= NTILES) break;
        const int tx = tile & 31;
        const int ty = tile >> 5;

#pragma unroll 1
        for (int it = 0; it < 10; it++) {
            const int i = it * 8 + warp;          // 0..79
            const int pix = i / 5;
            const int r = i - pix * 5;
            const int p = ((ty * 4 + (pix >> 2)) << 7) + tx * 4 + (pix & 3);
            const int l = r * HW + p;

            const float4 g = g_geom[l];           // broadcast

            const float px = g.x * t + g.z * omt - 0.5f;
            const float py = g.y * t + g.w * omt - 0.5f;

            const float px0 = fminf(fmaxf(floorf(px), 0.0f), 127.0f);
            const float py0 = fminf(fmaxf(floorf(py), 0.0f), 127.0f);
            const float px1 = fminf(px0 + 1.0f, 127.0f);
            const float py1 = fminf(py0 + 1.0f, 127.0f);

            const int ix0 = (int)px0, iy0 = (int)py0;
            const int ix1 = (int)px1, iy1 = (int)py1;

            const float w00 = (py1 - py) * (px1 - px);
            const float w10 = (py - py0) * (px1 - px);
            const float w01 = (py1 - py) * (px - px0);
            const float w11 = (py - py0) * (px - px0);

            const uint4* __restrict__ f00 = g_fthv + (iy0 * WW + ix0) * 2;
            const uint4* __restrict__ f10 = g_fthv + (iy1 * WW + ix0) * 2;
            const uint4* __restrict__ f01 = g_fthv + (iy0 * WW + ix1) * 2;
            const uint4* __restrict__ f11 = g_fthv + (iy1 * WW + ix1) * 2;

            float o16[16];
#pragma unroll
            for (int j = 0; j < 2; j++) {
                uint4 a = f00[j];
                uint4 b = f10[j];
                uint4 c = f01[j];
                uint4 d = f11[j];
                const unsigned av[4] = {a.x, a.y, a.z, a.w};
                const unsigned bv[4] = {b.x, b.y, b.z, b.w};
                const unsigned cv[4] = {c.x, c.y, c.z, c.w};
                const unsigned dv[4] = {d.x, d.y, d.z, d.w};
#pragma unroll
                for (int k = 0; k < 4; k++) {
                    float2 fa = h2f(av[k]);
                    float2 fb = h2f(bv[k]);
                    float2 fc = h2f(cv[k]);
                    float2 fd = h2f(dv[k]);
                    o16[j * 8 + 2 * k + 0] =
                        w00 * fa.x + w10 * fb.x + w01 * fc.x + w11 * fd.x;
                    o16[j * 8 + 2 * k + 1] =
                        w00 * fa.y + w10 * fb.y + w01 * fc.y + w11 * fd.y;
                }
            }

            float* __restrict__ o = out + (size_t)l * (CC * NPTS) + lane;
#pragma unroll
            for (int k = 0; k < 16; k++)
                __stcs(o + k * NPTS, o16[k]);
        }
    }

    // ================= epilogue: last block resets counters ================
    __syncthreads();
    if (tid == 0) {
        unsigned ticket = atomicAdd(&g_done, 1u);
        if (ticket == GRID - 1) {
            g_bar = 0;
            g_tile = 0;
            g_done = 0;
            __threadfence();
        }
    }
}

// ---------------------------------------------------------------------------
extern "C" void kernel_launch(void* const* d_in, const int* in_sizes, int n_in,
                              void* d_out, int out_size) {
    const float* md   = (const float*)d_in[0];
    const float* dis  = (const float*)d_in[1];
    const float* res  = (const float*)d_in[2];
    const float* feat = (const float*)d_in[3];
    const float* jloc = (const float*)d_in[4];
    const float* joff = (const float*)d_in[5];
    float* out = (float*)d_out;

    hawp_kernel<<<GRID, 256>>>(md, dis, res, feat, jloc, joff, out);
}